// round 2
// baseline (speedup 1.0000x reference)
#include <cuda_runtime.h>

// XY model log-density: out[s] = sum_i cos(x[up(i)] - x[i]) + cos(x[right(i)] - x[i])
// Lattice 64x64 (4096 sites), 16384 samples, BETA = 1.
//
// R2: each thread owns 16 CONTIGUOUS sites (quarter of one lattice row).
//  - own sites + up-neighbors loaded as LDS.128 (8 wide loads)
//  - 15/16 right-neighbors come from the thread's own registers
//  - 1 scalar LDS for the segment-boundary right neighbor
// LDS ops per thread: 48 scalar -> 8x128b + 1 scalar. Kills the L1 bottleneck.

#define LATTICE 4096
#define THREADS 256

__global__ __launch_bounds__(THREADS) void xy_hamiltonian_kernel(
    const float* __restrict__ state,
    float* __restrict__ out)
{
    __shared__ float sm[LATTICE];
    __shared__ float warp_sums[THREADS / 32];

    const int row = blockIdx.x;
    const int tid = threadIdx.x;
    const float4* __restrict__ rp4 =
        reinterpret_cast<const float4*>(state + (size_t)row * LATTICE);
    float4* sm4 = reinterpret_cast<float4*>(sm);

    // Cooperative coalesced load of the 16KB row
    #pragma unroll
    for (int k = 0; k < LATTICE / 4 / THREADS; k++) {
        int i = tid + k * THREADS;
        sm4[i] = rp4[i];
    }
    __syncthreads();

    // Thread t owns sites [16t, 16t+16)  == float4 indices [4t, 4t+4)
    const int f4base = 4 * tid;

    float x[16], u[16];
    #pragma unroll
    for (int c = 0; c < 4; c++) {
        float4 a = sm4[f4base + c];                          // own sites
        x[4 * c + 0] = a.x; x[4 * c + 1] = a.y;
        x[4 * c + 2] = a.z; x[4 * c + 3] = a.w;
        float4 b = sm4[(f4base + 16 + c) & (LATTICE / 4 - 1)]; // up neighbors (i+64 mod 4096)
        u[4 * c + 0] = b.x; u[4 * c + 1] = b.y;
        u[4 * c + 2] = b.z; u[4 * c + 3] = b.w;
    }

    // Right neighbor of the last owned site (site i = 16t+15):
    // col = i & 63 in {15,31,47,63}; right = (i & ~63) | ((i+1) & 63)
    const int ilast = 16 * tid + 15;
    const float xr_last = sm[(ilast & ~63) | ((ilast + 1) & 63)];

    float acc = 0.0f;
    #pragma unroll
    for (int j = 0; j < 16; j++) {
        float xr = (j < 15) ? x[j + 1] : xr_last;
        acc += __cosf(u[j] - x[j]);
        acc += __cosf(xr   - x[j]);
    }

    // Warp reduce
    #pragma unroll
    for (int o = 16; o > 0; o >>= 1)
        acc += __shfl_down_sync(0xffffffffu, acc, o);
    if ((tid & 31) == 0)
        warp_sums[tid >> 5] = acc;
    __syncthreads();

    if (tid < 8) {
        float v = warp_sums[tid];
        #pragma unroll
        for (int o = 4; o > 0; o >>= 1)
            v += __shfl_down_sync(0x000000ffu, v, o);
        if (tid == 0)
            out[row] = v;
    }
}

extern "C" void kernel_launch(void* const* d_in, const int* in_sizes, int n_in,
                              void* d_out, int out_size)
{
    const float* state = (const float*)d_in[0];
    // d_in[1] (shift table, int64) is reproduced arithmetically in-kernel.
    float* out = (float*)d_out;

    const int n_samples = in_sizes[0] / LATTICE;  // 16384
    xy_hamiltonian_kernel<<<n_samples, THREADS>>>(state, out);
}

// round 3
// speedup vs baseline: 2.0249x; 2.0249x over previous
#include <cuda_runtime.h>

// XY model log-density: out[s] = sum_i cos(x[up(i)] - x[i]) + cos(x[right(i)] - x[i])
// 64x64 lattice (4096 sites), 16384 samples, BETA = 1.
//
// R3: no shared memory. Each thread handles 4 float4 chunks (16 sites):
//   - own float4 + up-neighbor float4 via LDG.128 (L2 merges the overlap)
//   - 3/4 right-neighbors from the same float4's registers
//   - 4th right-neighbor via one SHFL.IDX from the next lane (wrap-aware)
// Small live state -> full register promotion (R2's local-mem spill fixed).

#define LATTICE 4096
#define THREADS 256

__global__ __launch_bounds__(THREADS) void xy_hamiltonian_kernel(
    const float* __restrict__ state,
    float* __restrict__ out)
{
    __shared__ float warp_sums[THREADS / 32];

    const int tid  = threadIdx.x;
    const int lane = tid & 31;
    const float4* __restrict__ rp4 =
        reinterpret_cast<const float4*>(state + (size_t)blockIdx.x * LATTICE);

    // Right-neighbor source lane: within each 16-lane group (one 64-site
    // lattice row), lane L's boundary right-neighbor is lane L+1's a.x,
    // wrapping to the group's first lane at col 63 (L % 16 == 15).
    const int src_lane = (lane & ~15) | ((lane + 1) & 15);

    float acc = 0.0f;
    #pragma unroll
    for (int k = 0; k < 4; k++) {
        const int m = tid + k * THREADS;                 // float4 index 0..1023
        const float4 a = rp4[m];                         // own sites 4m..4m+3
        const float4 b = rp4[(m + 16) & (LATTICE/4 - 1)];// up neighbors (+64 sites, periodic)
        const float xr3 = __shfl_sync(0xffffffffu, a.x, src_lane);

        acc += __cosf(b.x - a.x);   // up bonds
        acc += __cosf(b.y - a.y);
        acc += __cosf(b.z - a.z);
        acc += __cosf(b.w - a.w);
        acc += __cosf(a.y - a.x);   // right bonds (intra-float4)
        acc += __cosf(a.z - a.y);
        acc += __cosf(a.w - a.z);
        acc += __cosf(xr3 - a.w);   // right bond across float4 boundary
    }

    // Warp reduce
    #pragma unroll
    for (int o = 16; o > 0; o >>= 1)
        acc += __shfl_down_sync(0xffffffffu, acc, o);
    if (lane == 0)
        warp_sums[tid >> 5] = acc;
    __syncthreads();

    if (tid < 8) {
        float v = warp_sums[tid];
        #pragma unroll
        for (int o = 4; o > 0; o >>= 1)
            v += __shfl_down_sync(0x000000ffu, v, o);
        if (tid == 0)
            out[blockIdx.x] = v;
    }
}

extern "C" void kernel_launch(void* const* d_in, const int* in_sizes, int n_in,
                              void* d_out, int out_size)
{
    const float* state = (const float*)d_in[0];
    // d_in[1] (shift table, int64) is reproduced arithmetically in-kernel.
    float* out = (float*)d_out;

    const int n_samples = in_sizes[0] / LATTICE;  // 16384
    xy_hamiltonian_kernel<<<n_samples, THREADS>>>(state, out);
}